// round 1
// baseline (speedup 1.0000x reference)
#include <cuda_runtime.h>
#include <cstdint>

#define N_FRAMES 65536
#define H_DIM    512
#define GVDIM    640
#define VNUM     320
#define DDIM     128

// Scratch (device-global arrays: allocation-free per harness rules)
__device__ float g_logits[(size_t)N_FRAMES * GVDIM];   // 160 MiB
__device__ float g_marginal[GVDIM];

// ---------------------------------------------------------------------------
// ~1-ulp log for fp32 (cephes-style), immune to --use_fast_math substitution.
// Valid for normal positive x.
// ---------------------------------------------------------------------------
__device__ __forceinline__ float acc_logf(float x) {
    int   ix = __float_as_int(x);
    int   e  = ((ix >> 23) & 0xff) - 126;
    float m  = __int_as_float((ix & 0x007fffff) | 0x3f000000);   // [0.5, 1)
    if (m < 0.70710678118654752f) { m += m; e -= 1; }            // [sqrt(.5), sqrt(2))
    float f = m - 1.0f;                                          // exact
    float z = f * f;
    float p = 7.0376836292e-2f;
    p = fmaf(p, f, -1.1514610310e-1f);
    p = fmaf(p, f,  1.1676998740e-1f);
    p = fmaf(p, f, -1.2420140846e-1f);
    p = fmaf(p, f,  1.4249322787e-1f);
    p = fmaf(p, f, -1.6668057665e-1f);
    p = fmaf(p, f,  2.0000714765e-1f);
    p = fmaf(p, f, -2.4999993993e-1f);
    p = fmaf(p, f,  3.3333331174e-1f);
    p = p * f * z;
    float ef = (float)e;
    p = fmaf(-0.5f, z, p);
    float r = fmaf(ef, -2.12194440e-4f, p);
    r = r + f;
    r = fmaf(ef, 0.693359375f, r);
    return r;
}

// ---------------------------------------------------------------------------
// Init: zero the marginal accumulator (re-run every launch -> deterministic)
// ---------------------------------------------------------------------------
__global__ void init_kernel() {
    int i = threadIdx.x;
    if (i < GVDIM) g_marginal[i] = 0.0f;
}

// ---------------------------------------------------------------------------
// fp32 GEMM: C[65536,640] = A[65536,512] * W[512,640] + b
// BM=128, BN=64, BK=16, 128 threads, 8x8 per-thread tile.
// ---------------------------------------------------------------------------
#define BM 128
#define BN 64
#define BK 16

__global__ __launch_bounds__(128) void gemm_kernel(
    const float* __restrict__ A, const float* __restrict__ W,
    const float* __restrict__ bias)
{
    __shared__ float As[BK][BM + 4];   // +4 floats keeps 16B alignment, shifts banks
    __shared__ float Bs[BK][BN];

    const int tid      = threadIdx.x;
    const int block_m  = blockIdx.y * BM;
    const int block_n  = blockIdx.x * BN;

    const int tm = (tid >> 3) * 8;     // 0..120
    const int tn = (tid & 7) * 8;      // 0..56

    const int arow = tid;              // 0..127: one A row per thread
    const int brow = tid >> 3;         // 0..15
    const int bcol = (tid & 7) * 8;    // 0..56

    const float* Aptr = A + (size_t)(block_m + arow) * H_DIM;
    const float* Wbase = W + (size_t)brow * GVDIM + block_n + bcol;

    float acc[8][8];
#pragma unroll
    for (int i = 0; i < 8; i++)
#pragma unroll
        for (int j = 0; j < 8; j++) acc[i][j] = 0.0f;

    for (int k0 = 0; k0 < H_DIM; k0 += BK) {
        // A tile: 16 consecutive k per thread, store transposed As[k][m]
        float4 a0 = reinterpret_cast<const float4*>(Aptr + k0)[0];
        float4 a1 = reinterpret_cast<const float4*>(Aptr + k0)[1];
        float4 a2 = reinterpret_cast<const float4*>(Aptr + k0)[2];
        float4 a3 = reinterpret_cast<const float4*>(Aptr + k0)[3];
        // B tile: row brow, 8 cols
        float4 b0 = reinterpret_cast<const float4*>(Wbase + (size_t)k0 * GVDIM)[0];
        float4 b1 = reinterpret_cast<const float4*>(Wbase + (size_t)k0 * GVDIM)[1];

        As[ 0][arow] = a0.x; As[ 1][arow] = a0.y; As[ 2][arow] = a0.z; As[ 3][arow] = a0.w;
        As[ 4][arow] = a1.x; As[ 5][arow] = a1.y; As[ 6][arow] = a1.z; As[ 7][arow] = a1.w;
        As[ 8][arow] = a2.x; As[ 9][arow] = a2.y; As[10][arow] = a2.z; As[11][arow] = a2.w;
        As[12][arow] = a3.x; As[13][arow] = a3.y; As[14][arow] = a3.z; As[15][arow] = a3.w;
        *reinterpret_cast<float4*>(&Bs[brow][bcol])     = b0;
        *reinterpret_cast<float4*>(&Bs[brow][bcol + 4]) = b1;
        __syncthreads();

#pragma unroll
        for (int k = 0; k < BK; k++) {
            float4 av0 = *reinterpret_cast<const float4*>(&As[k][tm]);
            float4 av1 = *reinterpret_cast<const float4*>(&As[k][tm + 4]);
            float4 bv0 = *reinterpret_cast<const float4*>(&Bs[k][tn]);
            float4 bv1 = *reinterpret_cast<const float4*>(&Bs[k][tn + 4]);
            float av[8] = {av0.x, av0.y, av0.z, av0.w, av1.x, av1.y, av1.z, av1.w};
            float bv[8] = {bv0.x, bv0.y, bv0.z, bv0.w, bv1.x, bv1.y, bv1.z, bv1.w};
#pragma unroll
            for (int i = 0; i < 8; i++)
#pragma unroll
                for (int j = 0; j < 8; j++)
                    acc[i][j] = fmaf(av[i], bv[j], acc[i][j]);
        }
        __syncthreads();
    }

    float bb[8];
#pragma unroll
    for (int j = 0; j < 8; j++) bb[j] = bias[block_n + tn + j];

#pragma unroll
    for (int i = 0; i < 8; i++) {
        float* crow = g_logits + (size_t)(block_m + tm + i) * GVDIM + block_n + tn;
        float4 o0, o1;
        o0.x = acc[i][0] + bb[0]; o0.y = acc[i][1] + bb[1];
        o0.z = acc[i][2] + bb[2]; o0.w = acc[i][3] + bb[3];
        o1.x = acc[i][4] + bb[4]; o1.y = acc[i][5] + bb[5];
        o1.z = acc[i][6] + bb[6]; o1.w = acc[i][7] + bb[7];
        reinterpret_cast<float4*>(crow)[0] = o0;
        reinterpret_cast<float4*>(crow)[1] = o1;
    }
}

// ---------------------------------------------------------------------------
// Epilogue: one warp per (n,g) pair; 64 pairs per warp.
// - gumbel argmax -> codevector gather
// - noise-free softmax -> marginal accumulation (register partials, then atomics)
// ---------------------------------------------------------------------------
__global__ __launch_bounds__(256) void epilogue_kernel(
    const float* __restrict__ gumbel_u,
    const float* __restrict__ codevectors,
    float* __restrict__ out)
{
    const unsigned FULL = 0xffffffffu;
    const int warp = blockIdx.x * 8 + (threadIdx.x >> 5);
    const int lane = threadIdx.x & 31;

    float macc[2][10];
#pragma unroll
    for (int g = 0; g < 2; g++)
#pragma unroll
        for (int j = 0; j < 10; j++) macc[g][j] = 0.0f;

    const int p0 = warp * 64;
    for (int i = 0; i < 64; i++) {
        const int p = p0 + i;
        const int n = p >> 1;
        const int g = p & 1;
        const float* lrow = g_logits + (size_t)n * GVDIM + g * VNUM;
        const float* urow = gumbel_u + (size_t)p * VNUM;

        float l[10];
        float lmax  = -3.4e38f;
        float zbest = -3.4e38f;
        int   ibest = 0;
#pragma unroll
        for (int j = 0; j < 10; j++) {
            const int v = lane + j * 32;
            const float lv = lrow[v];
            l[j] = lv;
            lmax = fmaxf(lmax, lv);
            const float u = urow[v];
            const float t = -acc_logf(u);          // -log(u) in (0, 23.03]
            const float noise = -acc_logf(t);      // gumbel
            const float zv = lv + noise;           // tau-div & softmax are monotone
            if (zv > zbest) { zbest = zv; ibest = v; }
        }
        // warp max of logits (softmax stability)
#pragma unroll
        for (int off = 16; off; off >>= 1)
            lmax = fmaxf(lmax, __shfl_xor_sync(FULL, lmax, off));
        float e[10];
        float s = 0.0f;
#pragma unroll
        for (int j = 0; j < 10; j++) { e[j] = __expf(l[j] - lmax); s += e[j]; }
#pragma unroll
        for (int off = 16; off; off >>= 1)
            s += __shfl_xor_sync(FULL, s, off);
        const float rs = 1.0f / s;
#pragma unroll
        for (int j = 0; j < 10; j++) macc[g][j] = fmaf(e[j], rs, macc[g][j]);

        // warp argmax with lowest-index tie-break (matches jnp.argmax)
#pragma unroll
        for (int off = 16; off; off >>= 1) {
            const float zo = __shfl_xor_sync(FULL, zbest, off);
            const int   io = __shfl_xor_sync(FULL, ibest, off);
            if (zo > zbest || (zo == zbest && io < ibest)) { zbest = zo; ibest = io; }
        }

        // codes gather: 128 floats = 32 lanes x float4
        const float4* cvp = reinterpret_cast<const float4*>(
            codevectors + ((size_t)(g * VNUM + ibest)) * DDIM);
        float4* op = reinterpret_cast<float4*>(out + (size_t)n * 256 + g * DDIM);
        op[lane] = cvp[lane];
    }

#pragma unroll
    for (int g = 0; g < 2; g++)
#pragma unroll
        for (int j = 0; j < 10; j++)
            atomicAdd(&g_marginal[g * VNUM + j * 32 + lane], macc[g][j]);
}

// ---------------------------------------------------------------------------
// Perplexity: marginal -> sum_g exp(-sum_v m log(m+1e-7))
// ---------------------------------------------------------------------------
__global__ void perp_kernel(float* __restrict__ out, int out_size) {
    __shared__ float s[GVDIM];
    const int i = threadIdx.x;
    if (i < GVDIM) {
        const float m = g_marginal[i] * (1.0f / (float)N_FRAMES);
        s[i] = m * acc_logf(m + 1e-7f);
    }
    __syncthreads();
    if (i == 0) {
        float s0 = 0.0f, s1 = 0.0f;
        for (int v = 0; v < VNUM; v++) { s0 += s[v]; s1 += s[VNUM + v]; }
        const float perp = __expf(-s0) + __expf(-s1);
        if (out_size > N_FRAMES * 256) out[(size_t)N_FRAMES * 256] = perp;
    }
}

// ---------------------------------------------------------------------------
extern "C" void kernel_launch(void* const* d_in, const int* in_sizes, int n_in,
                              void* d_out, int out_size) {
    const float* hs = (const float*)d_in[0];   // [16,4096,512]
    const float* W  = (const float*)d_in[1];   // [512,640]
    const float* b  = (const float*)d_in[2];   // [640]
    const float* cv = (const float*)d_in[3];   // [640,128]
    const float* gu = (const float*)d_in[4];   // [131072,320]
    float* out = (float*)d_out;

    init_kernel<<<1, GVDIM>>>();

    dim3 ggrid(GVDIM / BN, N_FRAMES / BM);     // (10, 512)
    gemm_kernel<<<ggrid, 128>>>(hs, W, b);

    epilogue_kernel<<<256, 256>>>(gu, cv, out);   // 256*8 warps * 64 pairs = 131072

    perp_kernel<<<1, GVDIM>>>(out, out_size);
}

// round 3
// speedup vs baseline: 1.9615x; 1.9615x over previous
#include <cuda_runtime.h>
#include <cuda_fp16.h>
#include <cstdint>

#define N_FRAMES 65536
#define H_DIM    512
#define GVDIM    640
#define VNUM     320
#define DDIM     128

// --------------------------- device scratch --------------------------------
__device__ float g_logits[(size_t)N_FRAMES * GVDIM];   // 160 MiB
__device__ float g_marginal[GVDIM];
__device__ __half g_A0[(size_t)N_FRAMES * H_DIM];      // 64 MiB
__device__ __half g_A1[(size_t)N_FRAMES * H_DIM];      // 64 MiB
__device__ __half g_B0[GVDIM * H_DIM];                 // W^T split hi [640][512]
__device__ __half g_B1[GVDIM * H_DIM];                 // W^T split lo

// --------------------------- helpers ---------------------------------------
__device__ __forceinline__ uint32_t smem_u32(const void* p) {
    uint32_t a;
    asm("{ .reg .u64 t; cvta.to.shared.u64 t, %1; cvt.u32.u64 %0, t; }"
        : "=r"(a) : "l"(p));
    return a;
}

__device__ __forceinline__ void cp_async16(uint32_t saddr, const void* gaddr) {
    asm volatile("cp.async.cg.shared.global [%0], [%1], 16;"
                 :: "r"(saddr), "l"(gaddr) : "memory");
}

__device__ __forceinline__ void ldsm4(uint32_t r[4], uint32_t addr) {
    asm volatile("ldmatrix.sync.aligned.m8n8.x4.shared.b16 {%0,%1,%2,%3}, [%4];"
                 : "=r"(r[0]), "=r"(r[1]), "=r"(r[2]), "=r"(r[3]) : "r"(addr));
}

__device__ __forceinline__ void mma16816(float c[4], const uint32_t a[4],
                                         const uint32_t b[2]) {
    asm volatile(
        "mma.sync.aligned.m16n8k16.row.col.f32.f16.f16.f32 "
        "{%0,%1,%2,%3}, {%4,%5,%6,%7}, {%8,%9}, {%0,%1,%2,%3};"
        : "+f"(c[0]), "+f"(c[1]), "+f"(c[2]), "+f"(c[3])
        : "r"(a[0]), "r"(a[1]), "r"(a[2]), "r"(a[3]), "r"(b[0]), "r"(b[1]));
}

// ---------------------------------------------------------------------------
// ~1-ulp log (fast-math proof)
// ---------------------------------------------------------------------------
__device__ __forceinline__ float acc_logf(float x) {
    int   ix = __float_as_int(x);
    int   e  = ((ix >> 23) & 0xff) - 126;
    float m  = __int_as_float((ix & 0x007fffff) | 0x3f000000);
    if (m < 0.70710678118654752f) { m += m; e -= 1; }
    float f = m - 1.0f;
    float z = f * f;
    float p = 7.0376836292e-2f;
    p = fmaf(p, f, -1.1514610310e-1f);
    p = fmaf(p, f,  1.1676998740e-1f);
    p = fmaf(p, f, -1.2420140846e-1f);
    p = fmaf(p, f,  1.4249322787e-1f);
    p = fmaf(p, f, -1.6668057665e-1f);
    p = fmaf(p, f,  2.0000714765e-1f);
    p = fmaf(p, f, -2.4999993993e-1f);
    p = fmaf(p, f,  3.3333331174e-1f);
    p = p * f * z;
    float ef = (float)e;
    p = fmaf(-0.5f, z, p);
    float r = fmaf(ef, -2.12194440e-4f, p);
    r = r + f;
    r = fmaf(ef, 0.693359375f, r);
    return r;
}

// ---------------------------------------------------------------------------
__global__ void init_kernel() {
    int i = threadIdx.x;
    if (i < GVDIM) g_marginal[i] = 0.0f;
}

// ---------------------------------------------------------------------------
// fp16 2-way exact-residual splits
// ---------------------------------------------------------------------------
__device__ __forceinline__ void split2(float v, __half& h0, __half& h1) {
    h0 = __float2half_rn(v);
    h1 = __float2half_rn(v - __half2float(h0));
}

__global__ __launch_bounds__(1024) void split_a_kernel(const float* __restrict__ A) {
    size_t i = (size_t)blockIdx.x * blockDim.x + threadIdx.x;  // float4 index
    float4 x = reinterpret_cast<const float4*>(A)[i];
    float v[4] = {x.x, x.y, x.z, x.w};
    __half h0[4], h1[4];
#pragma unroll
    for (int c = 0; c < 4; c++) split2(v[c], h0[c], h1[c]);
    __half2* p0 = reinterpret_cast<__half2*>(g_A0);
    __half2* p1 = reinterpret_cast<__half2*>(g_A1);
    p0[2 * i]     = __half2(h0[0], h0[1]);
    p0[2 * i + 1] = __half2(h0[2], h0[3]);
    p1[2 * i]     = __half2(h1[0], h1[1]);
    p1[2 * i + 1] = __half2(h1[2], h1[3]);
}

// W[k][n] -> B[n][k]
__global__ __launch_bounds__(512) void split_b_kernel(const float* __restrict__ W) {
    int n = blockIdx.x;       // 0..639
    int k = threadIdx.x;      // 0..511
    float v = W[(size_t)k * GVDIM + n];
    __half h0, h1;
    split2(v, h0, h1);
    g_B0[(size_t)n * H_DIM + k] = h0;
    g_B1[(size_t)n * H_DIM + k] = h1;
}

// ---------------------------------------------------------------------------
// GEMM: logits[65536,640] = A*W + b via 4-term fp16 split on mma.sync HMMA.
// BM=128, BN=128, BK=32; 256 threads (8 warps, 2x4); warp tile 64x32.
// smem: double-buffered, padded 80B rows (conflict-free ldmatrix).
// ---------------------------------------------------------------------------
#define STG_BYTES  40960          // per stage: A(2x10240) + B(2x10240)
#define SPLIT_BYTES 10240         // 128 rows x 80B
#define SMEM_BYTES (2 * STG_BYTES)

__global__ __launch_bounds__(256, 2) void gemm_kernel(const float* __restrict__ bias) {
    extern __shared__ char smem[];
    const uint32_t sb = smem_u32(smem);
    const int tid  = threadIdx.x;
    const int wid  = tid >> 5;
    const int lane = tid & 31;
    const int wm = wid >> 2;           // 0..1
    const int wn = wid & 3;            // 0..3
    const int m0 = blockIdx.y * 128;
    const int n0 = blockIdx.x * 128;

    float acc[4][4][4];
#pragma unroll
    for (int mf = 0; mf < 4; mf++)
#pragma unroll
        for (int nf = 0; nf < 4; nf++)
#pragma unroll
            for (int c = 0; c < 4; c++) acc[mf][nf][c] = 0.0f;

    // ---- stage loader: 2048 x 16B chunks, 8 per thread ----
    auto issue_stage = [&](int s, int buf) {
        const int kbase = s * 32;
#pragma unroll
        for (int t = 0; t < 8; t++) {
            const int c     = tid + t * 256;      // 0..2047
            const int isB   = c >> 10;            // 0:A 1:B
            const int ci    = c & 1023;
            const int split = ci >> 9;            // 0..1
            const int row   = (ci >> 2) & 127;    // 0..127
            const int kc    = ci & 3;             // 0..3 (16B chunks)
            const __half* gp = isB ? (split ? g_B1 : g_B0)
                                   : (split ? g_A1 : g_A0);
            const int grow = (isB ? n0 : m0) + row;
            const char* ga = (const char*)(gp + (size_t)grow * H_DIM + kbase) + kc * 16;
            const uint32_t sa = sb + buf * STG_BYTES + isB * 20480 +
                                split * SPLIT_BYTES + row * 80 + kc * 16;
            cp_async16(sa, ga);
        }
        asm volatile("cp.async.commit_group;" ::: "memory");
    };

    issue_stage(0, 0);

    // per-lane ldmatrix address components
    const int a_row   = wm * 64 + (lane & 15);    // + mf*16
    const int a_kc    = (lane >> 4) * 16;         // byte
    const int b_row   = wn * 32 + ((lane >> 4) & 1) * 8 + (lane & 7);  // + p*16
    const int b_kc    = ((lane >> 3) & 1) * 16;

    for (int s = 0; s < 16; s++) {
        if (s + 1 < 16) {
            issue_stage(s + 1, (s + 1) & 1);
            asm volatile("cp.async.wait_group 1;" ::: "memory");
        } else {
            asm volatile("cp.async.wait_group 0;" ::: "memory");
        }
        __syncthreads();

        const uint32_t abase = sb + (s & 1) * STG_BYTES;
        const uint32_t bbase = abase + 20480;

#pragma unroll
        for (int ks = 0; ks < 2; ks++) {
            // B fragments: both splits, 2 pairs each (4 nfrags)
            uint32_t Bf[2][8];
#pragma unroll
            for (int s2 = 0; s2 < 2; s2++)
#pragma unroll
                for (int p = 0; p < 2; p++) {
                    uint32_t addr = bbase + s2 * SPLIT_BYTES +
                                    (b_row + p * 16) * 80 + ks * 32 + b_kc;
                    ldsm4(&Bf[s2][p * 4], addr);
                }
#pragma unroll
            for (int sa = 0; sa < 2; sa++) {
                uint32_t Af[4][4];
#pragma unroll
                for (int mf = 0; mf < 4; mf++) {
                    uint32_t addr = abase + sa * SPLIT_BYTES +
                                    (a_row + mf * 16) * 80 + ks * 32 + a_kc;
                    ldsm4(Af[mf], addr);
                }
#pragma unroll
                for (int sbb = 0; sbb < 2; sbb++)
#pragma unroll
                    for (int mf = 0; mf < 4; mf++)
#pragma unroll
                        for (int nf = 0; nf < 4; nf++)
                            mma16816(acc[mf][nf], Af[mf], &Bf[sbb][nf * 2]);
            }
        }
        __syncthreads();
    }

    // ---- store + bias (full 32B sectors) ----
    const int gID = lane >> 2;
    const int tig = lane & 3;
    float2 bv[4];
#pragma unroll
    for (int nf = 0; nf < 4; nf++)
        bv[nf] = *reinterpret_cast<const float2*>(bias + n0 + wn * 32 + nf * 8 + tig * 2);

#pragma unroll
    for (int mf = 0; mf < 4; mf++) {
        const int m = m0 + wm * 64 + mf * 16 + gID;
#pragma unroll
        for (int nf = 0; nf < 4; nf++) {
            const int n = n0 + wn * 32 + nf * 8 + tig * 2;
            float2 v0 = {acc[mf][nf][0] + bv[nf].x, acc[mf][nf][1] + bv[nf].y};
            float2 v1 = {acc[mf][nf][2] + bv[nf].x, acc[mf][nf][3] + bv[nf].y};
            *reinterpret_cast<float2*>(g_logits + (size_t)m * GVDIM + n)       = v0;
            *reinterpret_cast<float2*>(g_logits + (size_t)(m + 8) * GVDIM + n) = v1;
        }
    }
}

// ---------------------------------------------------------------------------
// Epilogue: one warp per (n,g) pair; 64 pairs per warp.
// ---------------------------------------------------------------------------
__global__ __launch_bounds__(256) void epilogue_kernel(
    const float* __restrict__ gumbel_u,
    const float* __restrict__ codevectors,
    float* __restrict__ out)
{
    const unsigned FULL = 0xffffffffu;
    const int warp = blockIdx.x * 8 + (threadIdx.x >> 5);
    const int lane = threadIdx.x & 31;

    float macc[2][10];
#pragma unroll
    for (int g = 0; g < 2; g++)
#pragma unroll
        for (int j = 0; j < 10; j++) macc[g][j] = 0.0f;

    const int p0 = warp * 64;
    for (int i = 0; i < 64; i++) {
        const int p = p0 + i;
        const int n = p >> 1;
        const int g = p & 1;
        const float* lrow = g_logits + (size_t)n * GVDIM + g * VNUM;
        const float* urow = gumbel_u + (size_t)p * VNUM;

        float l[10];
        float lmax  = -3.4e38f;
        float zbest = -3.4e38f;
        int   ibest = 0;
#pragma unroll
        for (int j = 0; j < 10; j++) {
            const int v = lane + j * 32;
            const float lv = lrow[v];
            l[j] = lv;
            lmax = fmaxf(lmax, lv);
            const float u = urow[v];
            const float t = -acc_logf(u);
            const float noise = -acc_logf(t);
            const float zv = lv + noise;
            if (zv > zbest) { zbest = zv; ibest = v; }
        }
#pragma unroll
        for (int off = 16; off; off >>= 1)
            lmax = fmaxf(lmax, __shfl_xor_sync(FULL, lmax, off));
        float e[10];
        float s = 0.0f;
#pragma unroll
        for (int j = 0; j < 10; j++) { e[j] = __expf(l[j] - lmax); s += e[j]; }
#pragma unroll
        for (int off = 16; off; off >>= 1)
            s += __shfl_xor_sync(FULL, s, off);
        const float rs = 1.0f / s;
#pragma unroll
        for (int j = 0; j < 10; j++) macc[g][j] = fmaf(e[j], rs, macc[g][j]);

#pragma unroll
        for (int off = 16; off; off >>= 1) {
            const float zo = __shfl_xor_sync(FULL, zbest, off);
            const int   io = __shfl_xor_sync(FULL, ibest, off);
            if (zo > zbest || (zo == zbest && io < ibest)) { zbest = zo; ibest = io; }
        }

        const float4* cvp = reinterpret_cast<const float4*>(
            codevectors + ((size_t)(g * VNUM + ibest)) * DDIM);
        float4* op = reinterpret_cast<float4*>(out + (size_t)n * 256 + g * DDIM);
        op[lane] = cvp[lane];
    }

#pragma unroll
    for (int g = 0; g < 2; g++)
#pragma unroll
        for (int j = 0; j < 10; j++)
            atomicAdd(&g_marginal[g * VNUM + j * 32 + lane], macc[g][j]);
}

// ---------------------------------------------------------------------------
__global__ void perp_kernel(float* __restrict__ out, int out_size) {
    __shared__ float s[GVDIM];
    const int i = threadIdx.x;
    if (i < GVDIM) {
        const float m = g_marginal[i] * (1.0f / (float)N_FRAMES);
        s[i] = m * acc_logf(m + 1e-7f);
    }
    __syncthreads();
    if (i == 0) {
        float s0 = 0.0f, s1 = 0.0f;
        for (int v = 0; v < VNUM; v++) { s0 += s[v]; s1 += s[VNUM + v]; }
        const float perp = __expf(-s0) + __expf(-s1);
        if (out_size > N_FRAMES * 256) out[(size_t)N_FRAMES * 256] = perp;
    }
}

// ---------------------------------------------------------------------------
extern "C" void kernel_launch(void* const* d_in, const int* in_sizes, int n_in,
                              void* d_out, int out_size) {
    const float* hs = (const float*)d_in[0];   // [16,4096,512]
    const float* W  = (const float*)d_in[1];   // [512,640]
    const float* b  = (const float*)d_in[2];   // [640]
    const float* cv = (const float*)d_in[3];   // [640,128]
    const float* gu = (const float*)d_in[4];   // [131072,320]
    float* out = (float*)d_out;

    init_kernel<<<1, GVDIM>>>();
    split_a_kernel<<<8192, 1024>>>(hs);
    split_b_kernel<<<GVDIM, 512>>>(W);

    cudaFuncSetAttribute(gemm_kernel,
                         cudaFuncAttributeMaxDynamicSharedMemorySize, SMEM_BYTES);
    gemm_kernel<<<dim3(5, 512), 256, SMEM_BYTES>>>(b);

    epilogue_kernel<<<256, 256>>>(gu, cv, out);
    perp_kernel<<<1, GVDIM>>>(out, out_size);
}

// round 4
// speedup vs baseline: 2.6349x; 1.3433x over previous
#include <cuda_runtime.h>
#include <cuda_fp16.h>
#include <cstdint>

#define N_FRAMES 65536
#define H_DIM    512
#define GVDIM    640
#define VNUM     320
#define DDIM     128

// --------------------------- device scratch --------------------------------
__device__ float g_logits[(size_t)N_FRAMES * GVDIM];   // 160 MiB
__device__ float g_marginal[GVDIM];
__device__ __half g_A0[(size_t)N_FRAMES * H_DIM];      // 64 MiB
__device__ __half g_A1[(size_t)N_FRAMES * H_DIM];      // 64 MiB
__device__ __half g_B0[GVDIM * H_DIM];                 // W^T split hi [640][512]
__device__ __half g_B1[GVDIM * H_DIM];                 // W^T split lo

// --------------------------- helpers ---------------------------------------
__device__ __forceinline__ uint32_t smem_u32(const void* p) {
    uint32_t a;
    asm("{ .reg .u64 t; cvta.to.shared.u64 t, %1; cvt.u32.u64 %0, t; }"
        : "=r"(a) : "l"(p));
    return a;
}

__device__ __forceinline__ void cp_async16(uint32_t saddr, const void* gaddr) {
    asm volatile("cp.async.cg.shared.global [%0], [%1], 16;"
                 :: "r"(saddr), "l"(gaddr) : "memory");
}

__device__ __forceinline__ void ldsm4(uint32_t r[4], uint32_t addr) {
    asm volatile("ldmatrix.sync.aligned.m8n8.x4.shared.b16 {%0,%1,%2,%3}, [%4];"
                 : "=r"(r[0]), "=r"(r[1]), "=r"(r[2]), "=r"(r[3]) : "r"(addr));
}

__device__ __forceinline__ void mma16816(float c[4], const uint32_t a[4],
                                         const uint32_t b[2]) {
    asm volatile(
        "mma.sync.aligned.m16n8k16.row.col.f32.f16.f16.f32 "
        "{%0,%1,%2,%3}, {%4,%5,%6,%7}, {%8,%9}, {%0,%1,%2,%3};"
        : "+f"(c[0]), "+f"(c[1]), "+f"(c[2]), "+f"(c[3])
        : "r"(a[0]), "r"(a[1]), "r"(a[2]), "r"(a[3]), "r"(b[0]), "r"(b[1]));
}

// ---------------------------------------------------------------------------
// ~1-ulp log (fast-math proof)
// ---------------------------------------------------------------------------
__device__ __forceinline__ float acc_logf(float x) {
    int   ix = __float_as_int(x);
    int   e  = ((ix >> 23) & 0xff) - 126;
    float m  = __int_as_float((ix & 0x007fffff) | 0x3f000000);
    if (m < 0.70710678118654752f) { m += m; e -= 1; }
    float f = m - 1.0f;
    float z = f * f;
    float p = 7.0376836292e-2f;
    p = fmaf(p, f, -1.1514610310e-1f);
    p = fmaf(p, f,  1.1676998740e-1f);
    p = fmaf(p, f, -1.2420140846e-1f);
    p = fmaf(p, f,  1.4249322787e-1f);
    p = fmaf(p, f, -1.6668057665e-1f);
    p = fmaf(p, f,  2.0000714765e-1f);
    p = fmaf(p, f, -2.4999993993e-1f);
    p = fmaf(p, f,  3.3333331174e-1f);
    p = p * f * z;
    float ef = (float)e;
    p = fmaf(-0.5f, z, p);
    float r = fmaf(ef, -2.12194440e-4f, p);
    r = r + f;
    r = fmaf(ef, 0.693359375f, r);
    return r;
}

// ---------------------------------------------------------------------------
// fp16 2-way exact-residual splits
// ---------------------------------------------------------------------------
__device__ __forceinline__ void split2(float v, __half& h0, __half& h1) {
    h0 = __float2half_rn(v);
    h1 = __float2half_rn(v - __half2float(h0));
}

__global__ __launch_bounds__(1024) void split_a_kernel(const float* __restrict__ A) {
    size_t i = (size_t)blockIdx.x * blockDim.x + threadIdx.x;  // float4 index
    float4 x = reinterpret_cast<const float4*>(A)[i];
    float v[4] = {x.x, x.y, x.z, x.w};
    __half h0[4], h1[4];
#pragma unroll
    for (int c = 0; c < 4; c++) split2(v[c], h0[c], h1[c]);
    __half2* p0 = reinterpret_cast<__half2*>(g_A0);
    __half2* p1 = reinterpret_cast<__half2*>(g_A1);
    p0[2 * i]     = __half2(h0[0], h0[1]);
    p0[2 * i + 1] = __half2(h0[2], h0[3]);
    p1[2 * i]     = __half2(h1[0], h1[1]);
    p1[2 * i + 1] = __half2(h1[2], h1[3]);
}

// W[k][n] -> B[n][k]; also zeroes g_marginal (fused init)
__global__ __launch_bounds__(512) void split_b_kernel(const float* __restrict__ W) {
    int n = blockIdx.x;       // 0..639
    int k = threadIdx.x;      // 0..511
    if (k == 0) g_marginal[n] = 0.0f;
    float v = W[(size_t)k * GVDIM + n];
    __half h0, h1;
    split2(v, h0, h1);
    g_B0[(size_t)n * H_DIM + k] = h0;
    g_B1[(size_t)n * H_DIM + k] = h1;
}

// ---------------------------------------------------------------------------
// GEMM: logits[65536,640] = A*W + b via 3-term fp16 split (a0b0+a0b1+a1b0).
// BM=128, BN=128, BK=32; 256 threads (8 warps, 2x4); warp tile 64x32.
// Double-buffered smem, 80B padded rows, ONE sync per stage.
// ---------------------------------------------------------------------------
#define STG_BYTES   40960         // per stage: A(2x10240) + B(2x10240)
#define SPLIT_BYTES 10240         // 128 rows x 80B
#define SMEM_BYTES  (2 * STG_BYTES)

__global__ __launch_bounds__(256, 2) void gemm_kernel(const float* __restrict__ bias) {
    extern __shared__ char smem[];
    const uint32_t sb = smem_u32(smem);
    const int tid  = threadIdx.x;
    const int wid  = tid >> 5;
    const int lane = tid & 31;
    const int wm = wid >> 2;           // 0..1
    const int wn = wid & 3;            // 0..3
    const int m0 = blockIdx.y * 128;
    const int n0 = blockIdx.x * 128;

    float acc[4][4][4];
#pragma unroll
    for (int mf = 0; mf < 4; mf++)
#pragma unroll
        for (int nf = 0; nf < 4; nf++)
#pragma unroll
            for (int c = 0; c < 4; c++) acc[mf][nf][c] = 0.0f;

    // ---- stage loader: 2048 x 16B chunks, 8 per thread ----
    auto issue_stage = [&](int s) {
        const int kbase = s * 32;
        const int buf   = s & 1;
#pragma unroll
        for (int t = 0; t < 8; t++) {
            const int c     = tid + t * 256;      // 0..2047
            const int isB   = c >> 10;            // 0:A 1:B
            const int ci    = c & 1023;
            const int split = ci >> 9;            // 0..1
            const int row   = (ci >> 2) & 127;    // 0..127
            const int kc    = ci & 3;             // 16B chunk
            const __half* gp = isB ? (split ? g_B1 : g_B0)
                                   : (split ? g_A1 : g_A0);
            const int grow = (isB ? n0 : m0) + row;
            const char* ga = (const char*)(gp + (size_t)grow * H_DIM + kbase) + kc * 16;
            const uint32_t sa = sb + buf * STG_BYTES + isB * 20480 +
                                split * SPLIT_BYTES + row * 80 + kc * 16;
            cp_async16(sa, ga);
        }
        asm volatile("cp.async.commit_group;" ::: "memory");
    };

    issue_stage(0);

    const int a_row = wm * 64 + (lane & 15);
    const int a_kc  = (lane >> 4) * 16;
    const int b_row = wn * 32 + ((lane >> 4) & 1) * 8 + (lane & 7);
    const int b_kc  = ((lane >> 3) & 1) * 16;

    for (int s = 0; s < 16; s++) {
        asm volatile("cp.async.wait_group 0;" ::: "memory");
        __syncthreads();                          // stage s visible; all past MMA(s-1)
        if (s + 1 < 16) issue_stage(s + 1);       // writes buf (s+1)&1 — safe

        const uint32_t abase = sb + (s & 1) * STG_BYTES;
        const uint32_t bbase = abase + 20480;

#pragma unroll
        for (int ks = 0; ks < 2; ks++) {
            uint32_t Bf[2][8];
#pragma unroll
            for (int s2 = 0; s2 < 2; s2++)
#pragma unroll
                for (int p = 0; p < 2; p++)
                    ldsm4(&Bf[s2][p * 4], bbase + s2 * SPLIT_BYTES +
                          (b_row + p * 16) * 80 + ks * 32 + b_kc);

            uint32_t Af[4][4];
#pragma unroll
            for (int mf = 0; mf < 4; mf++)
                ldsm4(Af[mf], abase + (a_row + mf * 16) * 80 + ks * 32 + a_kc);
            // a0*b0 and a0*b1
#pragma unroll
            for (int mf = 0; mf < 4; mf++)
#pragma unroll
                for (int nf = 0; nf < 4; nf++)
                    mma16816(acc[mf][nf], Af[mf], &Bf[0][nf * 2]);
#pragma unroll
            for (int mf = 0; mf < 4; mf++)
#pragma unroll
                for (int nf = 0; nf < 4; nf++)
                    mma16816(acc[mf][nf], Af[mf], &Bf[1][nf * 2]);
            // a1*b0
#pragma unroll
            for (int mf = 0; mf < 4; mf++)
                ldsm4(Af[mf], abase + SPLIT_BYTES + (a_row + mf * 16) * 80 + ks * 32 + a_kc);
#pragma unroll
            for (int mf = 0; mf < 4; mf++)
#pragma unroll
                for (int nf = 0; nf < 4; nf++)
                    mma16816(acc[mf][nf], Af[mf], &Bf[0][nf * 2]);
        }
    }

    // ---- store + bias ----
    const int gID = lane >> 2;
    const int tig = lane & 3;
    float2 bv[4];
#pragma unroll
    for (int nf = 0; nf < 4; nf++)
        bv[nf] = *reinterpret_cast<const float2*>(bias + n0 + wn * 32 + nf * 8 + tig * 2);

#pragma unroll
    for (int mf = 0; mf < 4; mf++) {
        const int m = m0 + wm * 64 + mf * 16 + gID;
#pragma unroll
        for (int nf = 0; nf < 4; nf++) {
            const int n = n0 + wn * 32 + nf * 8 + tig * 2;
            float2 v0 = {acc[mf][nf][0] + bv[nf].x, acc[mf][nf][1] + bv[nf].y};
            float2 v1 = {acc[mf][nf][2] + bv[nf].x, acc[mf][nf][3] + bv[nf].y};
            *reinterpret_cast<float2*>(g_logits + (size_t)m * GVDIM + n)       = v0;
            *reinterpret_cast<float2*>(g_logits + (size_t)(m + 8) * GVDIM + n) = v1;
        }
    }
}

// ---------------------------------------------------------------------------
// Epilogue: one warp per (n,g) pair; 16 pairs per warp; 1024 blocks.
// ---------------------------------------------------------------------------
__global__ __launch_bounds__(256) void epilogue_kernel(
    const float* __restrict__ gumbel_u,
    const float* __restrict__ codevectors,
    float* __restrict__ out)
{
    const unsigned FULL = 0xffffffffu;
    __shared__ float smar[GVDIM];
    const int tid  = threadIdx.x;
    const int warp = blockIdx.x * 8 + (tid >> 5);
    const int lane = tid & 31;

    for (int i = tid; i < GVDIM; i += 256) smar[i] = 0.0f;
    __syncthreads();

    float macc[2][10];
#pragma unroll
    for (int g = 0; g < 2; g++)
#pragma unroll
        for (int j = 0; j < 10; j++) macc[g][j] = 0.0f;

    const int p0 = warp * 16;
    for (int i = 0; i < 16; i++) {
        const int p = p0 + i;
        const int n = p >> 1;
        const int g = p & 1;
        const float* lrow = g_logits + (size_t)n * GVDIM + g * VNUM;
        const float* urow = gumbel_u + (size_t)p * VNUM;

        float l[10];
        float lmax  = -3.4e38f;
        float zbest = -3.4e38f;
        int   ibest = 0;
#pragma unroll
        for (int j = 0; j < 10; j++) {
            const int v = lane + j * 32;
            const float lv = lrow[v];
            l[j] = lv;
            lmax = fmaxf(lmax, lv);
            const float u = urow[v];
            const float t = -acc_logf(u);
            const float noise = -acc_logf(t);
            const float zv = lv + noise;
            if (zv > zbest) { zbest = zv; ibest = v; }
        }
#pragma unroll
        for (int off = 16; off; off >>= 1)
            lmax = fmaxf(lmax, __shfl_xor_sync(FULL, lmax, off));
        float e[10];
        float s = 0.0f;
#pragma unroll
        for (int j = 0; j < 10; j++) { e[j] = __expf(l[j] - lmax); s += e[j]; }
#pragma unroll
        for (int off = 16; off; off >>= 1)
            s += __shfl_xor_sync(FULL, s, off);
        const float rs = 1.0f / s;
#pragma unroll
        for (int j = 0; j < 10; j++) macc[g][j] = fmaf(e[j], rs, macc[g][j]);

#pragma unroll
        for (int off = 16; off; off >>= 1) {
            const float zo = __shfl_xor_sync(FULL, zbest, off);
            const int   io = __shfl_xor_sync(FULL, ibest, off);
            if (zo > zbest || (zo == zbest && io < ibest)) { zbest = zo; ibest = io; }
        }

        const float4* cvp = reinterpret_cast<const float4*>(
            codevectors + ((size_t)(g * VNUM + ibest)) * DDIM);
        float4* op = reinterpret_cast<float4*>(out + (size_t)n * 256 + g * DDIM);
        op[lane] = cvp[lane];
    }

    // block-level marginal reduction, then few global atomics
#pragma unroll
    for (int g = 0; g < 2; g++)
#pragma unroll
        for (int j = 0; j < 10; j++)
            atomicAdd(&smar[g * VNUM + j * 32 + lane], macc[g][j]);
    __syncthreads();
    for (int i = tid; i < GVDIM; i += 256)
        atomicAdd(&g_marginal[i], smar[i]);
}

// ---------------------------------------------------------------------------
__global__ void perp_kernel(float* __restrict__ out, int out_size) {
    __shared__ float s[GVDIM];
    const int i = threadIdx.x;
    if (i < GVDIM) {
        const float m = g_marginal[i] * (1.0f / (float)N_FRAMES);
        s[i] = m * acc_logf(m + 1e-7f);
    }
    __syncthreads();
    if (i == 0) {
        float s0 = 0.0f, s1 = 0.0f;
        for (int v = 0; v < VNUM; v++) { s0 += s[v]; s1 += s[VNUM + v]; }
        const float perp = __expf(-s0) + __expf(-s1);
        if (out_size > N_FRAMES * 256) out[(size_t)N_FRAMES * 256] = perp;
    }
}

// ---------------------------------------------------------------------------
extern "C" void kernel_launch(void* const* d_in, const int* in_sizes, int n_in,
                              void* d_out, int out_size) {
    const float* hs = (const float*)d_in[0];   // [16,4096,512]
    const float* W  = (const float*)d_in[1];   // [512,640]
    const float* b  = (const float*)d_in[2];   // [640]
    const float* cv = (const float*)d_in[3];   // [640,128]
    const float* gu = (const float*)d_in[4];   // [131072,320]
    float* out = (float*)d_out;

    split_a_kernel<<<8192, 1024>>>(hs);
    split_b_kernel<<<GVDIM, 512>>>(W);

    cudaFuncSetAttribute(gemm_kernel,
                         cudaFuncAttributeMaxDynamicSharedMemorySize, SMEM_BYTES);
    gemm_kernel<<<dim3(5, 512), 256, SMEM_BYTES>>>(b);

    epilogue_kernel<<<1024, 256>>>(gu, cv, out);
    perp_kernel<<<1, GVDIM>>>(out, out_size);
}

// round 5
// speedup vs baseline: 2.8446x; 1.0796x over previous
#include <cuda_runtime.h>
#include <cuda_fp16.h>
#include <cstdint>

#define N_FRAMES 65536
#define H_DIM    512
#define GVDIM    640
#define VNUM     320
#define DDIM     128

// --------------------------- device scratch --------------------------------
__device__ float g_logits[(size_t)N_FRAMES * GVDIM];   // 160 MiB
__device__ float g_marginal[GVDIM];
__device__ __half g_A0[(size_t)N_FRAMES * H_DIM];      // 64 MiB
__device__ __half g_A1[(size_t)N_FRAMES * H_DIM];      // 64 MiB
__device__ __half g_B0[GVDIM * H_DIM];                 // W^T split hi [640][512]
__device__ __half g_B1[GVDIM * H_DIM];                 // W^T split lo

// --------------------------- helpers ---------------------------------------
__device__ __forceinline__ uint32_t smem_u32(const void* p) {
    uint32_t a;
    asm("{ .reg .u64 t; cvta.to.shared.u64 t, %1; cvt.u32.u64 %0, t; }"
        : "=r"(a) : "l"(p));
    return a;
}

__device__ __forceinline__ void cp_async16(uint32_t saddr, const void* gaddr) {
    asm volatile("cp.async.cg.shared.global [%0], [%1], 16;"
                 :: "r"(saddr), "l"(gaddr) : "memory");
}

__device__ __forceinline__ void ldsm4(uint32_t r[4], uint32_t addr) {
    asm volatile("ldmatrix.sync.aligned.m8n8.x4.shared.b16 {%0,%1,%2,%3}, [%4];"
                 : "=r"(r[0]), "=r"(r[1]), "=r"(r[2]), "=r"(r[3]) : "r"(addr));
}

__device__ __forceinline__ void mma16816(float c[4], const uint32_t a[4],
                                         const uint32_t b[2]) {
    asm volatile(
        "mma.sync.aligned.m16n8k16.row.col.f32.f16.f16.f32 "
        "{%0,%1,%2,%3}, {%4,%5,%6,%7}, {%8,%9}, {%0,%1,%2,%3};"
        : "+f"(c[0]), "+f"(c[1]), "+f"(c[2]), "+f"(c[3])
        : "r"(a[0]), "r"(a[1]), "r"(a[2]), "r"(a[3]), "r"(b[0]), "r"(b[1]));
}

// ---------------------------------------------------------------------------
// ~1-ulp log (fast-math proof)
// ---------------------------------------------------------------------------
__device__ __forceinline__ float acc_logf(float x) {
    int   ix = __float_as_int(x);
    int   e  = ((ix >> 23) & 0xff) - 126;
    float m  = __int_as_float((ix & 0x007fffff) | 0x3f000000);
    if (m < 0.70710678118654752f) { m += m; e -= 1; }
    float f = m - 1.0f;
    float z = f * f;
    float p = 7.0376836292e-2f;
    p = fmaf(p, f, -1.1514610310e-1f);
    p = fmaf(p, f,  1.1676998740e-1f);
    p = fmaf(p, f, -1.2420140846e-1f);
    p = fmaf(p, f,  1.4249322787e-1f);
    p = fmaf(p, f, -1.6668057665e-1f);
    p = fmaf(p, f,  2.0000714765e-1f);
    p = fmaf(p, f, -2.4999993993e-1f);
    p = fmaf(p, f,  3.3333331174e-1f);
    p = p * f * z;
    float ef = (float)e;
    p = fmaf(-0.5f, z, p);
    float r = fmaf(ef, -2.12194440e-4f, p);
    r = r + f;
    r = fmaf(ef, 0.693359375f, r);
    return r;
}

// ---------------------------------------------------------------------------
// fp16 2-way exact-residual splits
// ---------------------------------------------------------------------------
__device__ __forceinline__ void split2(float v, __half& h0, __half& h1) {
    h0 = __float2half_rn(v);
    h1 = __float2half_rn(v - __half2float(h0));
}

__global__ __launch_bounds__(1024) void split_a_kernel(const float* __restrict__ A) {
    size_t i = (size_t)blockIdx.x * blockDim.x + threadIdx.x;  // float4 index
    float4 x = reinterpret_cast<const float4*>(A)[i];
    float v[4] = {x.x, x.y, x.z, x.w};
    __half h0[4], h1[4];
#pragma unroll
    for (int c = 0; c < 4; c++) split2(v[c], h0[c], h1[c]);
    __half2* p0 = reinterpret_cast<__half2*>(g_A0);
    __half2* p1 = reinterpret_cast<__half2*>(g_A1);
    p0[2 * i]     = __half2(h0[0], h0[1]);
    p0[2 * i + 1] = __half2(h0[2], h0[3]);
    p1[2 * i]     = __half2(h1[0], h1[1]);
    p1[2 * i + 1] = __half2(h1[2], h1[3]);
}

// W[k][n] -> B[n][k]; also zeroes g_marginal (fused init)
__global__ __launch_bounds__(512) void split_b_kernel(const float* __restrict__ W) {
    int n = blockIdx.x;       // 0..639
    int k = threadIdx.x;      // 0..511
    if (k == 0) g_marginal[n] = 0.0f;
    float v = W[(size_t)k * GVDIM + n];
    __half h0, h1;
    split2(v, h0, h1);
    g_B0[(size_t)n * H_DIM + k] = h0;
    g_B1[(size_t)n * H_DIM + k] = h1;
}

// ---------------------------------------------------------------------------
// GEMM: logits[65536,640] = A*W + b via 3-term fp16 split (a0b0+a0b1+a1b0).
// BM=128, BN=128, BK=32; 256 threads (8 warps, 2x4); warp tile 64x32.
// Double-buffered smem, 80B padded rows, ONE sync per stage.
// ---------------------------------------------------------------------------
#define STG_BYTES   40960         // per stage: A(2x10240) + B(2x10240)
#define SPLIT_BYTES 10240         // 128 rows x 80B
#define SMEM_BYTES  (2 * STG_BYTES)

__global__ __launch_bounds__(256, 2) void gemm_kernel(const float* __restrict__ bias) {
    extern __shared__ char smem[];
    const uint32_t sb = smem_u32(smem);
    const int tid  = threadIdx.x;
    const int wid  = tid >> 5;
    const int lane = tid & 31;
    const int wm = wid >> 2;           // 0..1
    const int wn = wid & 3;            // 0..3
    const int m0 = blockIdx.y * 128;
    const int n0 = blockIdx.x * 128;

    float acc[4][4][4];
#pragma unroll
    for (int mf = 0; mf < 4; mf++)
#pragma unroll
        for (int nf = 0; nf < 4; nf++)
#pragma unroll
            for (int c = 0; c < 4; c++) acc[mf][nf][c] = 0.0f;

    // ---- hoisted loader addressing (identical layout to R4) ----
    const int r0 = tid >> 2;                     // 0..63
    const int kc = tid & 3;                      // 16B chunk in row
    const __half* pA0 = g_A0 + (size_t)(m0 + r0) * H_DIM + kc * 8;
    const __half* pA1 = g_A1 + (size_t)(m0 + r0) * H_DIM + kc * 8;
    const __half* pB0 = g_B0 + (size_t)(n0 + r0) * H_DIM + kc * 8;
    const __half* pB1 = g_B1 + (size_t)(n0 + r0) * H_DIM + kc * 8;
    const uint32_t sA = sb + r0 * 80 + kc * 16;
    const size_t ROW64 = (size_t)64 * H_DIM;     // +64 rows in elements

    auto issue_stage = [&](int s) {
        const int off = s * 32;                  // elements
        const uint32_t buf = (uint32_t)(s & 1) * STG_BYTES;
        cp_async16(sA + buf,                      pA0 + off);
        cp_async16(sA + buf + 5120,               pA0 + off + ROW64);
        cp_async16(sA + buf + SPLIT_BYTES,        pA1 + off);
        cp_async16(sA + buf + SPLIT_BYTES + 5120, pA1 + off + ROW64);
        cp_async16(sA + buf + 20480,              pB0 + off);
        cp_async16(sA + buf + 20480 + 5120,       pB0 + off + ROW64);
        cp_async16(sA + buf + 30720,              pB1 + off);
        cp_async16(sA + buf + 30720 + 5120,       pB1 + off + ROW64);
        asm volatile("cp.async.commit_group;" ::: "memory");
    };

    issue_stage(0);

    const int a_row = wm * 64 + (lane & 15);
    const int a_kc  = (lane >> 4) * 16;
    const int b_row = wn * 32 + ((lane >> 4) & 1) * 8 + (lane & 7);
    const int b_kc  = ((lane >> 3) & 1) * 16;

    for (int s = 0; s < 16; s++) {
        asm volatile("cp.async.wait_group 0;" ::: "memory");
        __syncthreads();
        if (s + 1 < 16) issue_stage(s + 1);

        const uint32_t abase = sb + (s & 1) * STG_BYTES;
        const uint32_t bbase = abase + 20480;

#pragma unroll
        for (int ks = 0; ks < 2; ks++) {
            uint32_t Bf[2][8];
#pragma unroll
            for (int s2 = 0; s2 < 2; s2++)
#pragma unroll
                for (int p = 0; p < 2; p++)
                    ldsm4(&Bf[s2][p * 4], bbase + s2 * SPLIT_BYTES +
                          (b_row + p * 16) * 80 + ks * 32 + b_kc);

            uint32_t Af[4][4];
#pragma unroll
            for (int mf = 0; mf < 4; mf++)
                ldsm4(Af[mf], abase + (a_row + mf * 16) * 80 + ks * 32 + a_kc);
#pragma unroll
            for (int mf = 0; mf < 4; mf++)
#pragma unroll
                for (int nf = 0; nf < 4; nf++)
                    mma16816(acc[mf][nf], Af[mf], &Bf[0][nf * 2]);
#pragma unroll
            for (int mf = 0; mf < 4; mf++)
#pragma unroll
                for (int nf = 0; nf < 4; nf++)
                    mma16816(acc[mf][nf], Af[mf], &Bf[1][nf * 2]);
#pragma unroll
            for (int mf = 0; mf < 4; mf++)
                ldsm4(Af[mf], abase + SPLIT_BYTES + (a_row + mf * 16) * 80 + ks * 32 + a_kc);
#pragma unroll
            for (int mf = 0; mf < 4; mf++)
#pragma unroll
                for (int nf = 0; nf < 4; nf++)
                    mma16816(acc[mf][nf], Af[mf], &Bf[0][nf * 2]);
        }
    }

    // ---- store + bias ----
    const int gID = lane >> 2;
    const int tig = lane & 3;
    float2 bv[4];
#pragma unroll
    for (int nf = 0; nf < 4; nf++)
        bv[nf] = *reinterpret_cast<const float2*>(bias + n0 + wn * 32 + nf * 8 + tig * 2);

#pragma unroll
    for (int mf = 0; mf < 4; mf++) {
        const int m = m0 + wm * 64 + mf * 16 + gID;
#pragma unroll
        for (int nf = 0; nf < 4; nf++) {
            const int n = n0 + wn * 32 + nf * 8 + tig * 2;
            float2 v0 = {acc[mf][nf][0] + bv[nf].x, acc[mf][nf][1] + bv[nf].y};
            float2 v1 = {acc[mf][nf][2] + bv[nf].x, acc[mf][nf][3] + bv[nf].y};
            *reinterpret_cast<float2*>(g_logits + (size_t)m * GVDIM + n)       = v0;
            *reinterpret_cast<float2*>(g_logits + (size_t)(m + 8) * GVDIM + n) = v1;
        }
    }
}

// ---------------------------------------------------------------------------
// Epilogue: one warp per (n,g) pair; 32 pairs per warp; 1024 blocks x 128 thr.
// Approx-filter argmax: cheap __logf pass, exact acc_logf only for candidates.
// ---------------------------------------------------------------------------
__global__ __launch_bounds__(128) void epilogue_kernel(
    const float* __restrict__ gumbel_u,
    const float* __restrict__ codevectors,
    float* __restrict__ out)
{
    const unsigned FULL = 0xffffffffu;
    __shared__ float smar[GVDIM];
    const int tid  = threadIdx.x;
    const int warp = blockIdx.x * 4 + (tid >> 5);
    const int lane = tid & 31;

    for (int i = tid; i < GVDIM; i += 128) smar[i] = 0.0f;
    __syncthreads();

    float macc[2][10];
#pragma unroll
    for (int g = 0; g < 2; g++)
#pragma unroll
        for (int j = 0; j < 10; j++) macc[g][j] = 0.0f;

    const int p0 = warp * 32;
    for (int i = 0; i < 32; i++) {
        const int p = p0 + i;
        const int n = p >> 1;
        const int g = p & 1;
        const float* lrow = g_logits + (size_t)n * GVDIM + g * VNUM;
        const float* urow = gumbel_u + (size_t)p * VNUM;

        float l[10], u[10], za[10];
#pragma unroll
        for (int jj = 0; jj < 5; jj++) {
            const int e0 = 2 * (lane + 32 * jj);
            float2 lf = *reinterpret_cast<const float2*>(lrow + e0);
            float2 uf = *reinterpret_cast<const float2*>(urow + e0);
            l[2 * jj] = lf.x; l[2 * jj + 1] = lf.y;
            u[2 * jj] = uf.x; u[2 * jj + 1] = uf.y;
        }

        // approx pass (MUFU): za = l - log(-log u); zax over reliable u<=0.99
        float lmax = -3.4e38f, zax = -3.4e38f;
#pragma unroll
        for (int s = 0; s < 10; s++) {
            lmax = fmaxf(lmax, l[s]);
            const float t  = -__logf(u[s]);
            const float zv = l[s] - __logf(t);
            za[s] = zv;
            if (u[s] <= 0.99f) zax = fmaxf(zax, zv);
        }
#pragma unroll
        for (int off = 16; off; off >>= 1) {
            lmax = fmaxf(lmax, __shfl_xor_sync(FULL, lmax, off));
            zax  = fmaxf(zax,  __shfl_xor_sync(FULL, zax,  off));
        }
        const float thresh = zax - 1e-3f;

        // exact pass only for candidates
        float zbest = -3.4e38f;
        int   ibest = 0x7fffffff;
#pragma unroll
        for (int jj = 0; jj < 5; jj++)
#pragma unroll
            for (int q = 0; q < 2; q++) {
                const int s = 2 * jj + q;
                if (u[s] > 0.99f || za[s] >= thresh) {
                    const float te = -acc_logf(u[s]);
                    const float zv = l[s] - acc_logf(te);
                    const int v = 64 * jj + 2 * lane + q;
                    if (zv > zbest || (zv == zbest && v < ibest)) { zbest = zv; ibest = v; }
                }
            }
#pragma unroll
        for (int off = 16; off; off >>= 1) {
            const float zo = __shfl_xor_sync(FULL, zbest, off);
            const int   io = __shfl_xor_sync(FULL, ibest, off);
            if (zo > zbest || (zo == zbest && io < ibest)) { zbest = zo; ibest = io; }
        }

        // noise-free softmax -> marginal partials
        float e[10];
        float ssum = 0.0f;
#pragma unroll
        for (int s = 0; s < 10; s++) { e[s] = __expf(l[s] - lmax); ssum += e[s]; }
#pragma unroll
        for (int off = 16; off; off >>= 1)
            ssum += __shfl_xor_sync(FULL, ssum, off);
        const float rs = 1.0f / ssum;
#pragma unroll
        for (int s = 0; s < 10; s++) macc[g][s] = fmaf(e[s], rs, macc[g][s]);

        // codes gather
        const float4* cvp = reinterpret_cast<const float4*>(
            codevectors + ((size_t)(g * VNUM + ibest)) * DDIM);
        float4* op = reinterpret_cast<float4*>(out + (size_t)n * 256 + g * DDIM);
        op[lane] = cvp[lane];
    }

    // block-level marginal reduction, then few global atomics
#pragma unroll
    for (int g = 0; g < 2; g++)
#pragma unroll
        for (int jj = 0; jj < 5; jj++)
#pragma unroll
            for (int q = 0; q < 2; q++)
                atomicAdd(&smar[g * VNUM + 64 * jj + 2 * lane + q], macc[g][2 * jj + q]);
    __syncthreads();
    for (int i = tid; i < GVDIM; i += 128)
        atomicAdd(&g_marginal[i], smar[i]);
}

// ---------------------------------------------------------------------------
__global__ void perp_kernel(float* __restrict__ out, int out_size) {
    __shared__ float red[2][2];
    const int i    = threadIdx.x;          // 0..63
    const int grp  = i >> 5;               // 0..1
    const int lane = i & 31;
    float part = 0.0f;
    for (int v = lane; v < VNUM; v += 32) {
        const float m = g_marginal[grp * VNUM + v] * (1.0f / (float)N_FRAMES);
        part += m * acc_logf(m + 1e-7f);
    }
#pragma unroll
    for (int off = 16; off; off >>= 1)
        part += __shfl_xor_sync(0xffffffffu, part, off);
    if (lane == 0) red[grp][0] = part;
    __syncthreads();
    if (i == 0) {
        const float perp = __expf(-red[0][0]) + __expf(-red[1][0]);
        if (out_size > N_FRAMES * 256) out[(size_t)N_FRAMES * 256] = perp;
    }
}

// ---------------------------------------------------------------------------
extern "C" void kernel_launch(void* const* d_in, const int* in_sizes, int n_in,
                              void* d_out, int out_size) {
    const float* hs = (const float*)d_in[0];   // [16,4096,512]
    const float* W  = (const float*)d_in[1];   // [512,640]
    const float* b  = (const float*)d_in[2];   // [640]
    const float* cv = (const float*)d_in[3];   // [640,128]
    const float* gu = (const float*)d_in[4];   // [131072,320]
    float* out = (float*)d_out;

    split_b_kernel<<<GVDIM, 512>>>(W);
    split_a_kernel<<<8192, 1024>>>(hs);

    cudaFuncSetAttribute(gemm_kernel,
                         cudaFuncAttributeMaxDynamicSharedMemorySize, SMEM_BYTES);
    gemm_kernel<<<dim3(5, 512), 256, SMEM_BYTES>>>(b);

    epilogue_kernel<<<1024, 128>>>(gu, cv, out);
    perp_kernel<<<1, 64>>>(out, out_size);
}